// round 10
// baseline (speedup 1.0000x reference)
#include <cuda_runtime.h>

#define BB 64
#define PP 32768
#define OO 50
#define NPT 4
#define TPB_A 256
#define LH 16               // slices per batch
#define LHB (BB * LH)       // 1024 blocks
#define SLICE (PP / LH)     // 2048 priors per slice
#define BUCK 8192
#define BSH 19              // bucket = float_bits >> 19 (monotone for v >= 0)
#define CCAP 24576          // smem candidate cap in k_finalize

// ---------------- scratch (static device globals; zero-initialized at module load) ----------------
__device__ unsigned long long g_best_packed[BB * OO]; // reset by k_override each replay
__device__ int   g_match[BB * PP];
__device__ float g_lcneg[BB * PP];
__device__ int   g_hist[BB * BUCK];                   // reset by k_collect each replay
__device__ float g_pll[LHB], g_ppl[LHB];
__device__ int   g_ppc[LHB];
__device__ float g_sab[LHB];                          // sum of lc in buckets > B
__device__ int   g_cab[LHB];                          // count in buckets > B
__device__ float g_cand[BB * PP];
__device__ int   g_candcnt[BB];                       // reset by k_finalize each replay
__device__ int   g_B[BB], g_krem[BB], g_k[BB], g_np[BB];
__device__ float g_pllB[BB], g_pplB[BB], g_topk[BB];

__global__ void k_pad() {} // launch-order shims: put k_match at ncu capture slot #4

// slow path for one truth: recompute candidates, warp-reduce packed key, one atomic
#define SLOW_TRUTH(T, TB, TA, CUR)                                                 \
  {                                                                                \
    unsigned long long key = 0ull;                                                 \
    _Pragma("unroll")                                                              \
    for (int k = 0; k < NPT; k++) {                                                \
      float w_ = fminf(px1[k], (TB).z) - fmaxf(px0[k], (TB).x);                    \
      float h_ = fminf(py1[k], (TB).w) - fmaxf(py0[k], (TB).y);                    \
      float in_ = fmaxf(w_, 0.f) * fmaxf(h_, 0.f);                                 \
      float un_ = ((TA) + pab[k]) - in_;                                           \
      if (in_ >= (CUR) * un_) {                                                    \
        float iou_ = in_ / un_; /* IEEE div, matches ref exactly */                 \
        unsigned long long kk = ((unsigned long long)__float_as_uint(iou_) << 32)  \
                              | (unsigned)(~(pbase + k * TPB_A + tid));            \
        if (kk > key) key = kk;                                                    \
      }                                                                            \
    }                                                                              \
    _Pragma("unroll")                                                              \
    for (int o_ = 16; o_ > 0; o_ >>= 1) {                                          \
      unsigned long long other_ = __shfl_xor_sync(0xFFFFFFFFu, key, o_);           \
      if (other_ > key) key = other_;                                              \
    }                                                                              \
    if ((tid & 31) == 0 && key != 0ull) {                                          \
      atomicMax(&s_cur[(T)], (unsigned)(key >> 32));                               \
      atomicMax(&g_best_packed[b * OO + (T)], key); /* int max: order-invariant */ \
    }                                                                              \
  }

// ---------------- match: per-prior best truth + per-truth best prior ----------------
__global__ __launch_bounds__(TPB_A, 3) void k_match(const float* __restrict__ priors,
                                                    const float* __restrict__ targets) {
    const int b = blockIdx.y;
    __shared__ float4 s_box[OO];
    __shared__ float s_area[OO];
    __shared__ int s_lab[OO];
    __shared__ unsigned s_cur[OO];

    const int tid = threadIdx.x;
    if (tid < OO) {
        const float* t = targets + (b * OO + tid) * 5;
        float x0 = t[0], y0 = t[1], x1 = t[2], y1 = t[3];
        s_box[tid] = make_float4(x0, y0, x1, y1);
        s_area[tid] = (x1 - x0) * (y1 - y0);
        s_lab[tid] = (t[4] >= 0.f) ? 1 : 0;
        // seed pruning threshold from evolving global best: later waves skip the
        // discovery storm. Any stale value <= final max only prunes strictly-worse
        // candidates ('>=' keeps ties) -> final atomicMax result identical.
        unsigned seed = (unsigned)(g_best_packed[b * OO + tid] >> 32);
        unsigned tiny = __float_as_uint(1e-30f);
        s_cur[tid] = seed > tiny ? seed : tiny;
    }
    __syncthreads();

    const int pbase = blockIdx.x * (TPB_A * NPT);
    float px0[NPT], py0[NPT], px1[NPT], py1[NPT], pab[NPT];
    float bi[NPT], bu[NPT];
    int   bidx[NPT];
#pragma unroll
    for (int k = 0; k < NPT; k++) {
        int p = pbase + k * TPB_A + tid;
        float4 pr = reinterpret_cast<const float4*>(priors)[p];
        float hw = pr.z * 0.5f, hh = pr.w * 0.5f;
        px0[k] = pr.x - hw; py0[k] = pr.y - hh;
        px1[k] = pr.x + hw; py1[k] = pr.y + hh;
        pab[k] = (px1[k] - px0[k]) * (py1[k] - py0[k]);
        bi[k] = 0.f; bu[k] = 1.f; bidx[k] = 0;
    }

    const int wid = tid >> 5;
    for (int tt = 0; tt < OO; tt += 2) {
        int t0 = tt + wid * 6; if (t0 >= OO) t0 -= OO;
        const int t1 = t0 + 1;
        const float4 tb0 = s_box[t0];
        const float4 tb1 = s_box[t1];
        const float ta0 = s_area[t0], ta1 = s_area[t1];
        float cur0 = __uint_as_float(s_cur[t0]); // plain LDS; staleness OK (pruning only)
        float cur1 = __uint_as_float(s_cur[t1]);
        float slack0 = -1.f, slack1 = -1.f;
#pragma unroll
        for (int k = 0; k < NPT; k++) {
            float w0 = fminf(px1[k], tb0.z) - fmaxf(px0[k], tb0.x);
            float h0 = fminf(py1[k], tb0.w) - fmaxf(py0[k], tb0.y);
            float i0 = fmaxf(w0, 0.f) * fmaxf(h0, 0.f);
            float u0 = (ta0 + pab[k]) - i0;
            if (i0 * bu[k] > bi[k] * u0) { bi[k] = i0; bu[k] = u0; bidx[k] = t0; }
            slack0 = fmaxf(slack0, fmaf(-cur0, u0, i0));
            float w1 = fminf(px1[k], tb1.z) - fmaxf(px0[k], tb1.x);
            float h1 = fminf(py1[k], tb1.w) - fmaxf(py0[k], tb1.y);
            float i1 = fmaxf(w1, 0.f) * fmaxf(h1, 0.f);
            float u1 = (ta1 + pab[k]) - i1;
            if (i1 * bu[k] > bi[k] * u1) { bi[k] = i1; bu[k] = u1; bidx[k] = t1; }
            slack1 = fmaxf(slack1, fmaf(-cur1, u1, i1));
        }
        if (__any_sync(0xFFFFFFFFu, slack0 >= 0.f)) SLOW_TRUTH(t0, tb0, ta0, cur0)
        if (__any_sync(0xFFFFFFFFu, slack1 >= 0.f)) SLOW_TRUTH(t1, tb1, ta1, cur1)
    }

#pragma unroll
    for (int k = 0; k < NPT; k++) {
        int conf = (2.f * bi[k] >= bu[k]) ? s_lab[bidx[k]] : 0; // iou >= 0.5
        g_match[b * PP + pbase + k * TPB_A + tid] = (conf << 16) | bidx[k];
    }
}

// ---------------- override: force each truth's best prior (last-j-wins) + reset scratch --------
__global__ void k_override(const float* __restrict__ targets) {
    int i = blockIdx.x * blockDim.x + threadIdx.x;
    if (i >= BB * OO) return;
    int b = i / OO, j = i - b * OO;
    unsigned long long pk = g_best_packed[i];
    g_best_packed[i] = 0ull; // restore zero invariant for next graph replay
    int p = (pk == 0ull) ? 0 : (int)(~(unsigned)(pk & 0xFFFFFFFFull));
    int lab = (targets[i * 5 + 4] >= 0.f) ? 1 : 0;
    atomicMax(&g_match[b * PP + p], (1 << 30) | (j << 16) | lab);
}

// ---------------- losses + per-batch 8192-bucket histogram of negative lc ----------------
__global__ __launch_bounds__(256) void k_losshist(const float* __restrict__ arm_loc,
                                                  const float* __restrict__ arm_conf,
                                                  const float* __restrict__ priors,
                                                  const float* __restrict__ targets) {
    __shared__ int s_h[BUCK]; // 32KB
    __shared__ float s_rf[8], s_rf2[8];
    __shared__ int s_ri[8];
    const int bx = blockIdx.x;
    const int b = bx >> 4, slice = bx & (LH - 1);
    const int tid = threadIdx.x, lane = tid & 31, w = tid >> 5;
    for (int i = tid; i < BUCK; i += 256) s_h[i] = 0;
    __syncthreads();

    float ll = 0.f, plc = 0.f; int pc = 0;
    const int base = b * PP + slice * SLICE;
    for (int it = 0; it < SLICE / 256; it++) { // 8 iters
        const int gid = base + it * 256 + tid;
        const int p = gid & (PP - 1);
        const int m = g_match[gid];
        int conf, idx;
        if (m & (1 << 30)) { idx = (m >> 16) & 0x3FFF; conf = m & 1; }
        else               { conf = m >> 16;           idx = m & 0xFFFF; }

        float2 c = reinterpret_cast<const float2*>(arm_conf)[gid];
        float dd = conf ? (c.x - c.y) : (c.y - c.x);
        float lc = fmaxf(dd, 0.f) + __logf(1.f + __expf(-fabsf(dd))); // lse - picked
        bool pos = conf > 0;
        g_lcneg[gid] = pos ? -1.0f : lc;
        if (!pos) {
            atomicAdd(&s_h[__float_as_uint(lc) >> BSH], 1);
        } else {
            pc++; plc += lc;
            float4 pr = reinterpret_cast<const float4*>(priors)[p];
            const float* t = targets + (b * OO + idx) * 5;
            float tx0 = t[0], ty0 = t[1], tx1 = t[2], ty1 = t[3];
            float gcx = ((tx0 + tx1) * 0.5f - pr.x) / (0.1f * pr.z);
            float gcy = ((ty0 + ty1) * 0.5f - pr.y) / (0.1f * pr.w);
            float gw = __logf((tx1 - tx0) / pr.z) * 5.0f;
            float gh = __logf((ty1 - ty0) / pr.w) * 5.0f;
            float4 l = reinterpret_cast<const float4*>(arm_loc)[gid];
            float d, ad;
            d = l.x - gcx; ad = fabsf(d); ll += (ad < 1.f) ? 0.5f * d * d : ad - 0.5f;
            d = l.y - gcy; ad = fabsf(d); ll += (ad < 1.f) ? 0.5f * d * d : ad - 0.5f;
            d = l.z - gw;  ad = fabsf(d); ll += (ad < 1.f) ? 0.5f * d * d : ad - 0.5f;
            d = l.w - gh;  ad = fabsf(d); ll += (ad < 1.f) ? 0.5f * d * d : ad - 0.5f;
        }
    }
    __syncthreads();
    // flush histogram (spread atomics across 64*8192 addresses)
    for (int i = tid; i < BUCK; i += 256) {
        int v = s_h[i];
        if (v) atomicAdd(&g_hist[b * BUCK + i], v);
    }
    // fixed-tree reduction of (ll, plc, pc)
    for (int o = 16; o > 0; o >>= 1) {
        ll  += __shfl_down_sync(0xFFFFFFFFu, ll, o);
        plc += __shfl_down_sync(0xFFFFFFFFu, plc, o);
        pc  += __shfl_down_sync(0xFFFFFFFFu, pc, o);
    }
    if (lane == 0) { s_rf[w] = ll; s_rf2[w] = plc; s_ri[w] = pc; }
    __syncthreads();
    if (tid == 0) {
        float L = 0.f, Pl = 0.f; int C = 0;
        for (int i = 0; i < 8; i++) { L += s_rf[i]; Pl += s_rf2[i]; C += s_ri[i]; }
        g_pll[bx] = L; g_ppl[bx] = Pl; g_ppc[bx] = C;
    }
}

// ---------------- pick threshold bucket per batch ----------------
__global__ __launch_bounds__(256) void k_bucket() {
    const int b = blockIdx.x, tid = threadIdx.x;
    __shared__ int s_incl[256];
    __shared__ int s_npos;
    if (tid < 32) {
        int v = (tid < LH) ? g_ppc[b * LH + tid] : 0;
        for (int o = 8; o > 0; o >>= 1) v += __shfl_down_sync(0xFFFFFFFFu, v, o);
        if (tid == 0) s_npos = v;
    }
    // descending chunk sums: thread t owns buckets [hi-31, hi], hi = 8191-32t
    const int hi = BUCK - 1 - 32 * tid;
    int s = 0;
    for (int d = 0; d < 32; d++) s += g_hist[b * BUCK + hi - d];
    s_incl[tid] = s;
    __syncthreads();
    for (int o = 1; o < 256; o <<= 1) { // Hillis-Steele inclusive scan
        int add = (tid >= o) ? s_incl[tid - o] : 0;
        __syncthreads();
        s_incl[tid] += add;
        __syncthreads();
    }
    const int total = s_incl[255];
    const int np = s_npos;
    long long kk = 3ll * (long long)np;
    if (kk > PP - 1) kk = PP - 1;
    if (kk > total) kk = total;
    const int k = (int)kk;
    if (tid == 0) { g_np[b] = np; g_k[b] = k; if (k == 0) { g_B[b] = -1; g_krem[b] = 0; } }
    const int excl = tid ? s_incl[tid - 1] : 0;
    if (k > 0 && excl < k && k <= s_incl[tid]) {
        int c = excl;
        for (int d = 0; d < 32; d++) {
            int j = hi - d;
            int cj = g_hist[b * BUCK + j];
            if (c + cj >= k) { g_B[b] = j; g_krem[b] = k - c; break; }
            c += cj;
        }
    }
}

// ---------------- collect: sum above bucket B, gather bucket-B candidates, re-zero hist ----------
__global__ __launch_bounds__(256) void k_collect() {
    const int bx = blockIdx.x;
    const int b = bx >> 4, slice = bx & (LH - 1);
    const int tid = threadIdx.x, lane = tid & 31, w = tid >> 5;
    const int B = g_B[b];
    float sab = 0.f; int cab = 0;
    const int base = b * PP + slice * SLICE;
    for (int it = 0; it < SLICE / 256; it++) {
        float v = g_lcneg[base + it * 256 + tid];
        if (v >= 0.f) {
            int bk = (int)(__float_as_uint(v) >> BSH);
            if (bk > B) { sab += v; cab++; }
            else if (bk == B) {
                int ix = atomicAdd(&g_candcnt[b], 1);
                g_cand[b * PP + ix] = v;
            }
        }
    }
    // re-zero this slice of the histogram for next replay
    for (int i = tid; i < BUCK / LH; i += 256)
        g_hist[b * BUCK + slice * (BUCK / LH) + i] = 0;
    // reduce partials
    for (int o = 16; o > 0; o >>= 1) {
        sab += __shfl_down_sync(0xFFFFFFFFu, sab, o);
        cab += __shfl_down_sync(0xFFFFFFFFu, cab, o);
    }
    __shared__ float s_rf[8];
    __shared__ int s_ri[8];
    if (lane == 0) { s_rf[w] = sab; s_ri[w] = cab; }
    __syncthreads();
    if (tid == 0) {
        float S = 0.f; int C = 0;
        for (int i = 0; i < 8; i++) { S += s_rf[i]; C += s_ri[i]; }
        g_sab[bx] = S; g_cab[bx] = C;
    }
}

// ---------------- finalize per batch: exact k-th value T among candidates, topk sum ----------
__global__ __launch_bounds__(256) void k_finalize() {
    extern __shared__ float s_c[]; // CCAP floats
    const int b = blockIdx.x, tid = threadIdx.x, lane = tid & 31, w = tid >> 5;
    __shared__ float sh_sab, sh_L, sh_Pl;
    __shared__ float s_rf[8];
    __shared__ int s_ri[8];

    // reduce the LH=16 slice partials
    if (tid < 32) {
        float sab = 0.f, L = 0.f, Pl = 0.f;
        if (tid < LH) {
            sab = g_sab[b * LH + tid];
            L = g_pll[b * LH + tid];
            Pl = g_ppl[b * LH + tid];
        }
        for (int o = 8; o > 0; o >>= 1) {
            sab += __shfl_down_sync(0xFFFFFFFFu, sab, o);
            L   += __shfl_down_sync(0xFFFFFFFFu, L, o);
            Pl  += __shfl_down_sync(0xFFFFFFFFu, Pl, o);
        }
        if (tid == 0) { sh_sab = sab; sh_L = L; sh_Pl = Pl; }
    }
    __syncthreads();

    const int n = g_candcnt[b];
    const int krem = g_krem[b], k = g_k[b];
    const float* cp;
    if (n <= CCAP) {
        for (int i = tid; i < n; i += 256) s_c[i] = g_cand[b * PP + i];
        cp = s_c;
    } else {
        cp = &g_cand[b * PP]; // correct-but-slow fallback (never expected)
    }
    __syncthreads();

    // T = min{ v in candidates : #(candidates > v) < krem }  (order-invariant)
    float tloc = 3.4e38f;
    if (k > 0) {
        for (int j = tid; j < n; j += 256) {
            float v = cp[j];
            int cg = 0;
            for (int i = 0; i < n; i++) cg += (cp[i] > v) ? 1 : 0;
            if (cg < krem && v < tloc) tloc = v;
        }
    }
    for (int o = 16; o > 0; o >>= 1)
        tloc = fminf(tloc, __shfl_down_sync(0xFFFFFFFFu, tloc, o));
    if (lane == 0) s_rf[w] = tloc;
    __syncthreads();
    __shared__ float sh_T;
    if (tid == 0) {
        float T = s_rf[0];
        for (int i = 1; i < 8; i++) T = fminf(T, s_rf[i]);
        sh_T = T;
    }
    __syncthreads();
    const float T = sh_T;

    // sum/count candidates strictly above T
    float sc = 0.f; int cc = 0;
    for (int j = tid; j < n; j += 256) {
        float v = cp[j];
        if (v > T) { sc += v; cc++; }
    }
    for (int o = 16; o > 0; o >>= 1) {
        sc += __shfl_down_sync(0xFFFFFFFFu, sc, o);
        cc += __shfl_down_sync(0xFFFFFFFFu, cc, o);
    }
    if (lane == 0) { s_rf[w] = sc; s_ri[w] = cc; }
    __syncthreads();
    if (tid == 0) {
        float S = 0.f; int C = 0;
        for (int i = 0; i < 8; i++) { S += s_rf[i]; C += s_ri[i]; }
        g_topk[b] = (k > 0) ? (sh_sab + S + (float)(krem - C) * T) : 0.f;
        g_pllB[b] = sh_L;
        g_pplB[b] = sh_Pl;
        g_candcnt[b] = 0; // restore zero invariant for next replay
    }
}

// ---------------- finalize (64 threads, fixed trees -> deterministic) ----------------
__global__ void k_final(float* __restrict__ out) {
    const int tid = threadIdx.x; // 64
    __shared__ float s_l[64], s_p[64], s_t[64];
    __shared__ int s_n[64];
    s_l[tid] = g_pllB[tid]; s_p[tid] = g_pplB[tid];
    s_t[tid] = g_topk[tid]; s_n[tid] = g_np[tid];
    __syncthreads();
    for (int o = 32; o > 0; o >>= 1) {
        if (tid < o) {
            s_l[tid] += s_l[tid + o]; s_p[tid] += s_p[tid + o];
            s_t[tid] += s_t[tid + o]; s_n[tid] += s_n[tid + o];
        }
        __syncthreads();
    }
    if (tid == 0) {
        float fn = (float)s_n[0];
        out[0] = s_l[0] / fn;
        out[1] = (s_p[0] + s_t[0]) / fn;
    }
}

extern "C" void kernel_launch(void* const* d_in, const int* in_sizes, int n_in,
                              void* d_out, int out_size) {
    const float* arm_loc  = (const float*)d_in[0];
    const float* arm_conf = (const float*)d_in[1];
    const float* priors   = (const float*)d_in[4];
    const float* targets  = (const float*)d_in[5];
    float* out = (float*)d_out;

    (void)in_sizes; (void)n_in; (void)out_size;

    static int smem_set = 0;
    if (!smem_set) {
        cudaFuncSetAttribute(k_finalize, cudaFuncAttributeMaxDynamicSharedMemorySize, CCAP * 4);
        smem_set = 1;
    }

    k_pad<<<1, 32>>>();
    k_pad<<<1, 32>>>();
    k_pad<<<1, 32>>>();
    k_match<<<dim3(PP / (TPB_A * NPT), BB), TPB_A>>>(priors, targets);
    k_override<<<(BB * OO + 127) / 128, 128>>>(targets);
    k_losshist<<<LHB, 256>>>(arm_loc, arm_conf, priors, targets);
    k_bucket<<<BB, 256>>>();
    k_collect<<<LHB, 256>>>();
    k_finalize<<<BB, 256, CCAP * 4>>>();
    k_final<<<1, 64>>>(out);
}